// round 7
// baseline (speedup 1.0000x reference)
#include <cuda_runtime.h>
#include <math.h>

#define RR 2048
#define NEN 16
#define NALLY 15
#define HH 64
#define OD 256
#define FD 10
#define KK 650

__device__ float g_W2p[KK*OD];
__device__ float g_EmbEn[RR*OD];
__device__ float g_EmbAlSum[RR*OD];
__device__ float g_PassEmb[RR*3];

typedef unsigned long long ull;

__device__ __forceinline__ ull ffma2(ull a, ull b, ull c) {
    ull d; asm("fma.rn.f32x2 %0, %1, %2, %3;" : "=l"(d) : "l"(a), "l"(b), "l"(c)); return d;
}
__device__ __forceinline__ ull fadd2(ull a, ull b) {
    ull d; asm("add.rn.f32x2 %0, %1, %2;" : "=l"(d) : "l"(a), "l"(b)); return d;
}
__device__ __forceinline__ ull pack2(float x, float y) {
    ull d; asm("mov.b64 %0, {%1, %2};" : "=l"(d) : "f"(x), "f"(y)); return d;
}
__device__ __forceinline__ float2 unpack2(ull v) {
    float2 r; asm("mov.b64 {%0, %1}, %2;" : "=f"(r.x), "=f"(r.y) : "l"(v)); return r;
}

// ---------------------------------------------------------------------------
// W2p[kk, hd*64+j] = sum_h W2full_al[kk, hd*64+h] * pw1[h*64+j]
__global__ void __launch_bounds__(256) w2p_kernel(const float* __restrict__ ha_w2,
                                                  const float* __restrict__ ha_b2,
                                                  const float* __restrict__ pw1) {
    __shared__ float wrow[256];
    const int kk = blockIdx.x;
    const int o  = threadIdx.x;
    float v;
    if (kk < 640) { int k = kk/10, i = kk - k*10; v = ha_w2[k*2560 + i*256 + o]; }
    else          { v = ha_b2[(kk-640)*256 + o]; }
    wrow[o] = v;
    __syncthreads();
    const int hd = o >> 6, j = o & 63;
    float s = 0.f;
#pragma unroll
    for (int h = 0; h < 64; h++) s = fmaf(wrow[hd*64 + h], __ldg(pw1 + h*64 + j), s);
    g_W2p[kk*256 + o] = s;
}

// ---------------------------------------------------------------------------
// Fused summed bilinear for BOTH entity types. blockIdx<128 -> enemy, else ally.
// 16 agents per block; rows zero-padded to 16 (padded e=0 => contribution 0).
// 256 threads: half = tid>>7 covers half of the kk range; f32x2 smem reduction.
__global__ void __launch_bounds__(256) summed_both_kernel(
    const float* __restrict__ enemy, const float* __restrict__ ally,
    const float* __restrict__ eW1, const float* __restrict__ eB1,
    const float* __restrict__ eW2, const float* __restrict__ eB2,
    const float* __restrict__ aW1, const float* __restrict__ aB1,
    const float* __restrict__ aW2, const float* __restrict__ aB2)
{
    __shared__ __align__(16) float a_sh[KK*16];   // [kk][agent]; reused as reduction buf
    __shared__ float e_sh[16*161];                // [agent][rr*10+i]
    const int tid = threadIdx.x;
    const bool EN = blockIdx.x < 128;
    const int bid = EN ? blockIdx.x : blockIdx.x - 128;
    const int ag0 = bid * 16;
    const float* feats = EN ? enemy : ally;
    const float* W1 = EN ? eW1 : aW1;
    const float* B1 = EN ? eB1 : aB1;
    const float* W2 = EN ? eW2 : aW2;
    const float* B2 = EN ? eB2 : aB2;
    const int strideK = EN ? 2820 : 2560;
    const int per = EN ? (16*FD) : (NALLY*FD);   // floats per agent in gmem

    // stage e, zero-padding ally row 15
    for (int idx = tid; idx < 16*160; idx += 256) {
        int a = idx / 160, rem = idx - a*160;
        float v = 0.f;
        if (rem < per) v = feats[(ag0 + a)*per + rem];
        e_sh[a*161 + rem] = v;
    }
    __syncthreads();

    // build A tile: 4 (k,agent) pairs per thread (256*4 = 1024 = 64*16)
#pragma unroll
    for (int p = 0; p < 4; p++) {
        int idx = tid + p*256;
        int a = idx & 15, k = idx >> 4;
        const float* ea = e_sh + a*161;
        float h[16];
#pragma unroll
        for (int rr = 0; rr < 16; rr++) {
            float s = B1[k];
#pragma unroll
            for (int i = 0; i < FD; i++) s = fmaf(ea[rr*FD + i], __ldg(W1 + i*HH + k), s);
            h[rr] = fmaxf(s, 0.f);
        }
#pragma unroll
        for (int i = 0; i < FD; i++) {
            float s = 0.f;
#pragma unroll
            for (int rr = 0; rr < 16; rr++) s = fmaf(h[rr], ea[rr*FD + i], s);
            a_sh[(k*10 + i)*16 + a] = s;
        }
    }
    // bias rows: sum of e over entities (padded rows contribute 0)
    if (tid < 160) {
        int a = tid & 15, i = tid >> 4;
        const float* ea = e_sh + a*161;
        float s = 0.f;
#pragma unroll
        for (int rr = 0; rr < 16; rr++) s += ea[rr*FD + i];
        a_sh[(640 + i)*16 + a] = s;
    }
    __syncthreads();

    const int half = tid >> 7, lane = tid & 127;
    const int c0 = lane * 2;
    ull acc[8][2];
#pragma unroll
    for (int p = 0; p < 8; p++) { acc[p][0] = 0ull; acc[p][1] = 0ull; }

    // half 0: k in [0,32); half 1: k in [32,64) + bias lanes
    const int kbeg = half ? 32 : 0, kend = half ? 64 : 32;
    for (int k = kbeg; k < kend; k++) {
        const float* wk = W2 + k*strideK + c0;
#pragma unroll
        for (int i = 0; i < 10; i++) {
            float2 wv = __ldg((const float2*)(wk + i*OD));
            ull w0 = pack2(wv.x, wv.x), w1d = pack2(wv.y, wv.y);
            const ulonglong2* ar = (const ulonglong2*)(a_sh + (k*10 + i)*16);
#pragma unroll
            for (int q = 0; q < 4; q++) {
                ulonglong2 av = ar[q];
                acc[2*q  ][0] = ffma2(av.x, w0,  acc[2*q  ][0]);
                acc[2*q  ][1] = ffma2(av.x, w1d, acc[2*q  ][1]);
                acc[2*q+1][0] = ffma2(av.y, w0,  acc[2*q+1][0]);
                acc[2*q+1][1] = ffma2(av.y, w1d, acc[2*q+1][1]);
            }
        }
    }
    if (half) {
#pragma unroll
        for (int i = 0; i < 10; i++) {
            float2 wv = __ldg((const float2*)(B2 + i*OD + c0));
            ull w0 = pack2(wv.x, wv.x), w1d = pack2(wv.y, wv.y);
            const ulonglong2* ar = (const ulonglong2*)(a_sh + (640 + i)*16);
#pragma unroll
            for (int q = 0; q < 4; q++) {
                ulonglong2 av = ar[q];
                acc[2*q  ][0] = ffma2(av.x, w0,  acc[2*q  ][0]);
                acc[2*q  ][1] = ffma2(av.x, w1d, acc[2*q  ][1]);
                acc[2*q+1][0] = ffma2(av.y, w0,  acc[2*q+1][0]);
                acc[2*q+1][1] = ffma2(av.y, w1d, acc[2*q+1][1]);
            }
        }
    }

    // cross-half reduction: reuse a_sh (dead after mainloop)
    ull* red = (ull*)a_sh;
    __syncthreads();
    if (half) {
#pragma unroll
        for (int p = 0; p < 8; p++) {
            red[(p*2 + 0)*128 + lane] = acc[p][0];
            red[(p*2 + 1)*128 + lane] = acc[p][1];
        }
    }
    __syncthreads();
    if (!half) {
        float* outp = EN ? g_EmbEn : g_EmbAlSum;
#pragma unroll
        for (int p = 0; p < 8; p++) {
            acc[p][0] = fadd2(acc[p][0], red[(p*2 + 0)*128 + lane]);
            acc[p][1] = fadd2(acc[p][1], red[(p*2 + 1)*128 + lane]);
            float2 f0 = unpack2(acc[p][0]);
            float2 f1 = unpack2(acc[p][1]);
            *(ull*)&outp[(ag0 + 2*p    )*OD + c0] = pack2(f0.x, f1.x);
            *(ull*)&outp[(ag0 + 2*p + 1)*OD + c0] = pack2(f0.y, f1.y);
        }
    }
}

// ---------------------------------------------------------------------------
// Ally passing path (unchanged from R4-passing): per-row GEMM vs W2p + epilogue
__global__ void __launch_bounds__(128) ally_pass_kernel(
    const float* __restrict__ feats,
    const float* __restrict__ W1, const float* __restrict__ B1,
    const float* __restrict__ pb1, const float* __restrict__ pw2,
    const float* __restrict__ pb2)
{
    __shared__ __align__(16) float a_sh[KK*16];
    __shared__ __align__(16) float h_sh[HH*16];
    __shared__ __align__(16) float e_sh[16*FD];
    const int tid = threadIdx.x;
    const int r0 = blockIdx.x;
    const int rowbase = r0 * NALLY;

    for (int idx = tid; idx < 16*FD; idx += 128) {
        float v = 0.f;
        if (idx < NALLY*FD) v = feats[rowbase*FD + idx];
        e_sh[idx] = v;
    }
    __syncthreads();

#pragma unroll
    for (int p = 0; p < 8; p++) {
        int idx = tid + p*128;
        int rr = idx & 15, k = idx >> 4;
        float s = 0.f;
        if (rr < NALLY) {
            s = B1[k];
#pragma unroll
            for (int i = 0; i < FD; i++) s = fmaf(e_sh[rr*FD + i], __ldg(W1 + i*HH + k), s);
            s = fmaxf(s, 0.f);
        }
        h_sh[idx] = s;
    }
    __syncthreads();

    for (int idx = tid; idx < KK*16; idx += 128) {
        int kk = idx >> 4, rr = idx & 15;
        float v;
        if (kk < 640) {
            int k = kk / 10, i = kk - k*10;
            v = h_sh[k*16 + rr] * e_sh[rr*FD + i];
        } else {
            v = e_sh[rr*FD + (kk - 640)];
        }
        a_sh[idx] = v;
    }
    __syncthreads();

    const int c0 = tid * 2;
    ull acc[8][2];
#pragma unroll
    for (int p = 0; p < 8; p++) { acc[p][0] = 0ull; acc[p][1] = 0ull; }

#pragma unroll 10
    for (int kk = 0; kk < KK; kk++) {
        float2 wv = __ldg((const float2*)(g_W2p + kk*OD + c0));
        ull w0 = pack2(wv.x, wv.x), w1d = pack2(wv.y, wv.y);
        const ulonglong2* ar = (const ulonglong2*)(a_sh + kk*16);
#pragma unroll
        for (int q = 0; q < 4; q++) {
            ulonglong2 av = ar[q];
            acc[2*q  ][0] = ffma2(av.x, w0,  acc[2*q  ][0]);
            acc[2*q  ][1] = ffma2(av.x, w1d, acc[2*q  ][1]);
            acc[2*q+1][0] = ffma2(av.y, w0,  acc[2*q+1][0]);
            acc[2*q+1][1] = ffma2(av.y, w1d, acc[2*q+1][1]);
        }
    }

    __syncthreads();
    float* t_sh = a_sh;
    const float bb0 = pb1[c0 & 63];
    const float bb1 = pb1[(c0 + 1) & 63];
#pragma unroll
    for (int p = 0; p < 8; p++) {
        float2 f0 = unpack2(acc[p][0]);
        float2 f1 = unpack2(acc[p][1]);
        *(ull*)(t_sh + c0*20 + 2*p)     = pack2(fmaxf(f0.x + bb0, 0.f), fmaxf(f0.y + bb0, 0.f));
        *(ull*)(t_sh + (c0+1)*20 + 2*p) = pack2(fmaxf(f1.x + bb1, 0.f), fmaxf(f1.y + bb1, 0.f));
    }
    __syncthreads();

    float* p_sh = h_sh;
    if (tid < 96) {
        int hd = tid / 24, rem = tid - hd*24, cc = rem >> 3, rp = rem & 7;
        ull ap = 0ull;
#pragma unroll 8
        for (int m = 0; m < 64; m++) {
            float wv = __ldg(pw2 + m*3 + cc);
            ull wd = pack2(wv, wv);
            ull tv = *(const ull*)(t_sh + (hd*64 + m)*20 + 2*rp);
            ap = ffma2(tv, wd, ap);
        }
        float2 f = unpack2(ap);
        p_sh[(hd*3 + cc)*16 + 2*rp]     = f.x;
        p_sh[(hd*3 + cc)*16 + 2*rp + 1] = f.y;
    }
    __syncthreads();

    if (tid < 3) {
        float mx = -INFINITY;
        float bb = pb2[tid];
        for (int row = 0; row < NALLY; row++) {
            float v = 0.25f * (p_sh[(0*3 + tid)*16 + row] + p_sh[(1*3 + tid)*16 + row] +
                               p_sh[(2*3 + tid)*16 + row] + p_sh[(3*3 + tid)*16 + row]) + bb;
            mx = fmaxf(mx, v);
        }
        g_PassEmb[r0*3 + tid] = mx;
    }
}

// ---------------------------------------------------------------------------
// Final: own-embed + merger softmax + GRU (float4 weight loads) + fc2 + concat
__global__ void __launch_bounds__(64) final_kernel(
    const float* __restrict__ own,
    const float* __restrict__ fc1_w, const float* __restrict__ fc1_b,
    const float* __restrict__ merger_w,
    const float* __restrict__ hstate,
    const float* __restrict__ wih, const float* __restrict__ whh,
    const float* __restrict__ bih, const float* __restrict__ bhh,
    const float* __restrict__ fc2_w1, const float* __restrict__ fc2_b1,
    const float* __restrict__ fc2_w2, const float* __restrict__ fc2_b2,
    float* __restrict__ out_q, float* __restrict__ out_h) {
    __shared__ float own_sh[32], x_sh[64], h_sh[64], hh_sh[64], t_sh[64];
    const int r = blockIdx.x, j = threadIdx.x;
    if (j < 30) own_sh[j] = own[r*30 + j];
    h_sh[j] = hstate[r*64 + j];
    __syncthreads();

    float eo = fc1_b[j];
#pragma unroll
    for (int i = 0; i < 30; i++) eo = fmaf(own_sh[i], fc1_w[i*64 + j], eo);

    float w0 = merger_w[j], w1v = merger_w[64+j], w2v = merger_w[128+j], w3v = merger_w[192+j];
    float mx = fmaxf(fmaxf(w0, w1v), fmaxf(w2v, w3v));
    float e0 = expf(w0-mx), e1 = expf(w1v-mx), e2 = expf(w2v-mx), e3 = expf(w3v-mx);
    float inv = 1.f / (e0+e1+e2+e3);
    const float* en = g_EmbEn + r*OD;
    const float* al = g_EmbAlSum + r*OD;
    float m = e0*inv*(en[j] + al[j]) + e1*inv*(en[64+j] + al[64+j])
            + e2*inv*(en[128+j] + al[128+j]) + e3*inv*(en[192+j] + al[192+j]);

    float x = fmaxf(eo + m, 0.f);
    x_sh[j] = x;
    __syncthreads();

    float gi[3], gh[3];
#pragma unroll
    for (int t = 0; t < 3; t++) {
        int g = t*64 + j;
        float si = bih[g], sh = bhh[g];
        const float4* wi4 = (const float4*)(wih + g*64);
        const float4* wh4 = (const float4*)(whh + g*64);
#pragma unroll 4
        for (int k4 = 0; k4 < 16; k4++) {
            float4 a = __ldg(wi4 + k4);
            float4 b = __ldg(wh4 + k4);
            si = fmaf(x_sh[4*k4+0], a.x, si); si = fmaf(x_sh[4*k4+1], a.y, si);
            si = fmaf(x_sh[4*k4+2], a.z, si); si = fmaf(x_sh[4*k4+3], a.w, si);
            sh = fmaf(h_sh[4*k4+0], b.x, sh); sh = fmaf(h_sh[4*k4+1], b.y, sh);
            sh = fmaf(h_sh[4*k4+2], b.z, sh); sh = fmaf(h_sh[4*k4+3], b.w, sh);
        }
        gi[t] = si; gh[t] = sh;
    }
    float rg = 1.f/(1.f + expf(-(gi[0]+gh[0])));
    float zg = 1.f/(1.f + expf(-(gi[1]+gh[1])));
    float ng = tanhf(gi[2] + rg*gh[2]);
    float hh = (1.f - zg)*ng + zg*h_sh[j];
    hh_sh[j] = hh;
    out_h[r*64 + j] = hh;
    __syncthreads();

    float tt = fc2_b1[j];
#pragma unroll 8
    for (int k = 0; k < 64; k++) tt = fmaf(hh_sh[k], fc2_w1[k*64 + j], tt);
    t_sh[j] = fmaxf(tt, 0.f);
    __syncthreads();

    if (j < 19) {
        float q = fc2_b2[j];
        for (int mm = 0; mm < 64; mm++) q = fmaf(t_sh[mm], fc2_w2[mm*19 + j], q);
        int col = (j < 9) ? j : j + 3;
        out_q[r*22 + col] = q;
    }
    if (j < 3) out_q[r*22 + 9 + j] = g_PassEmb[r*3 + j];
}

extern "C" void kernel_launch(void* const* d_in, const int* in_sizes, int n_in,
                              void* d_out, int out_size) {
    const float* own    = (const float*)d_in[1];
    const float* ally   = (const float*)d_in[2];
    const float* enemy  = (const float*)d_in[3];
    const float* hstate = (const float*)d_in[4];
    const float* fc1_w  = (const float*)d_in[5];
    const float* fc1_b  = (const float*)d_in[6];
    const float* he_w1  = (const float*)d_in[7];
    const float* he_b1  = (const float*)d_in[8];
    const float* he_w2  = (const float*)d_in[9];
    const float* he_b2  = (const float*)d_in[10];
    const float* ha_w1  = (const float*)d_in[11];
    const float* ha_b1  = (const float*)d_in[12];
    const float* ha_w2  = (const float*)d_in[13];
    const float* ha_b2  = (const float*)d_in[14];
    const float* merger = (const float*)d_in[15];
    const float* wih    = (const float*)d_in[16];
    const float* whh    = (const float*)d_in[17];
    const float* bih    = (const float*)d_in[18];
    const float* bhh    = (const float*)d_in[19];
    const float* fc2_w1 = (const float*)d_in[20];
    const float* fc2_b1 = (const float*)d_in[21];
    const float* fc2_w2 = (const float*)d_in[22];
    const float* fc2_b2 = (const float*)d_in[23];
    const float* pw1    = (const float*)d_in[24];
    const float* pb1    = (const float*)d_in[25];
    const float* pw2    = (const float*)d_in[26];
    const float* pb2    = (const float*)d_in[27];

    float* out   = (float*)d_out;
    float* out_q = out;              // [2048, 22]
    float* out_h = out + RR*22;      // [2048, 64]

    w2p_kernel<<<KK, 256>>>(ha_w2, ha_b2, pw1);
    summed_both_kernel<<<256, 256>>>(enemy, ally,
                                     he_w1, he_b1, he_w2, he_b2,
                                     ha_w1, ha_b1, ha_w2, ha_b2);
    ally_pass_kernel<<<RR, 128>>>(ally, ha_w1, ha_b1, pb1, pw2, pb2);
    final_kernel<<<RR, 64>>>(own, fc1_w, fc1_b, merger, hstate,
                             wih, whh, bih, bhh,
                             fc2_w1, fc2_b1, fc2_w2, fc2_b2,
                             out_q, out_h);
}

// round 9
// speedup vs baseline: 1.4431x; 1.4431x over previous
#include <cuda_runtime.h>
#include <math.h>

#define RR 2048
#define NEN 16
#define NALLY 15
#define HH 64
#define OD 256
#define FD 10
#define KK 650

__device__ float g_W2p[KK*OD];
__device__ float g_EmbEn[RR*OD];
__device__ float g_EmbAlSum[RR*OD];
__device__ float g_PassEmb[RR*3];

typedef unsigned long long ull;

__device__ __forceinline__ ull ffma2(ull a, ull b, ull c) {
    ull d; asm("fma.rn.f32x2 %0, %1, %2, %3;" : "=l"(d) : "l"(a), "l"(b), "l"(c)); return d;
}
__device__ __forceinline__ ull pack2(float x, float y) {
    ull d; asm("mov.b64 %0, {%1, %2};" : "=l"(d) : "f"(x), "f"(y)); return d;
}
__device__ __forceinline__ float2 unpack2(ull v) {
    float2 r; asm("mov.b64 {%0, %1}, %2;" : "=f"(r.x), "=f"(r.y) : "l"(v)); return r;
}

// ---------------------------------------------------------------------------
__global__ void __launch_bounds__(256) w2p_kernel(const float* __restrict__ ha_w2,
                                                  const float* __restrict__ ha_b2,
                                                  const float* __restrict__ pw1) {
    __shared__ float wrow[256];
    const int kk = blockIdx.x;
    const int o  = threadIdx.x;
    float v;
    if (kk < 640) { int k = kk/10, i = kk - k*10; v = ha_w2[k*2560 + i*256 + o]; }
    else          { v = ha_b2[(kk-640)*256 + o]; }
    wrow[o] = v;
    __syncthreads();
    const int hd = o >> 6, j = o & 63;
    float s = 0.f;
#pragma unroll
    for (int h = 0; h < 64; h++) s = fmaf(wrow[hd*64 + h], __ldg(pw1 + h*64 + j), s);
    g_W2p[kk*256 + o] = s;
}

// ---------------------------------------------------------------------------
// Summed bilinear (R4 version, measured-good): 16 agents/block, grid RR/16.
template<int NR, bool ENEMY>
__global__ void __launch_bounds__(128) summed_kernel(
    const float* __restrict__ feats,
    const float* __restrict__ W1, const float* __restrict__ B1,
    const float* __restrict__ W2, const float* __restrict__ B2, int strideK)
{
    __shared__ __align__(16) float a_sh[KK*16];
    __shared__ float e_sh[16*161];
    const int tid = threadIdx.x;
    const int ag0 = blockIdx.x * 16;
    for (int idx = tid; idx < 16*NR*FD; idx += 128) {
        int a = idx / (NR*FD), rem = idx - a*(NR*FD);
        e_sh[a*161 + rem] = feats[(ag0*NR)*FD + idx];
    }
    __syncthreads();
#pragma unroll
    for (int p = 0; p < 8; p++) {
        int idx = tid + p*128;
        int a = idx & 15, k = idx >> 4;
        const float* ea = e_sh + a*161;
        float h[NR];
#pragma unroll
        for (int rr = 0; rr < NR; rr++) {
            float s = B1[k];
#pragma unroll
            for (int i = 0; i < FD; i++) s = fmaf(ea[rr*FD + i], __ldg(W1 + i*HH + k), s);
            h[rr] = fmaxf(s, 0.f);
        }
#pragma unroll
        for (int i = 0; i < FD; i++) {
            float s = 0.f;
#pragma unroll
            for (int rr = 0; rr < NR; rr++) s = fmaf(h[rr], ea[rr*FD + i], s);
            a_sh[(k*10 + i)*16 + a] = s;
        }
    }
    for (int idx = tid; idx < 160; idx += 128) {
        int a = idx & 15, i = idx >> 4;
        const float* ea = e_sh + a*161;
        float s = 0.f;
#pragma unroll
        for (int rr = 0; rr < NR; rr++) s += ea[rr*FD + i];
        a_sh[(640 + i)*16 + a] = s;
    }
    __syncthreads();
    const int c0 = tid * 2;
    ull acc[8][2];
#pragma unroll
    for (int p = 0; p < 8; p++) { acc[p][0] = 0ull; acc[p][1] = 0ull; }
    for (int k = 0; k < 64; k++) {
        const float* wk = W2 + k*strideK + c0;
#pragma unroll
        for (int i = 0; i < 10; i++) {
            float2 wv = __ldg((const float2*)(wk + i*OD));
            ull w0 = pack2(wv.x, wv.x), w1d = pack2(wv.y, wv.y);
            const ulonglong2* ar = (const ulonglong2*)(a_sh + (k*10 + i)*16);
#pragma unroll
            for (int q = 0; q < 4; q++) {
                ulonglong2 av = ar[q];
                acc[2*q  ][0] = ffma2(av.x, w0,  acc[2*q  ][0]);
                acc[2*q  ][1] = ffma2(av.x, w1d, acc[2*q  ][1]);
                acc[2*q+1][0] = ffma2(av.y, w0,  acc[2*q+1][0]);
                acc[2*q+1][1] = ffma2(av.y, w1d, acc[2*q+1][1]);
            }
        }
    }
#pragma unroll
    for (int i = 0; i < 10; i++) {
        float2 wv = __ldg((const float2*)(B2 + i*OD + c0));
        ull w0 = pack2(wv.x, wv.x), w1d = pack2(wv.y, wv.y);
        const ulonglong2* ar = (const ulonglong2*)(a_sh + (640 + i)*16);
#pragma unroll
        for (int q = 0; q < 4; q++) {
            ulonglong2 av = ar[q];
            acc[2*q  ][0] = ffma2(av.x, w0,  acc[2*q  ][0]);
            acc[2*q  ][1] = ffma2(av.x, w1d, acc[2*q  ][1]);
            acc[2*q+1][0] = ffma2(av.y, w0,  acc[2*q+1][0]);
            acc[2*q+1][1] = ffma2(av.y, w1d, acc[2*q+1][1]);
        }
    }
    float* outp = ENEMY ? g_EmbEn : g_EmbAlSum;
#pragma unroll
    for (int p = 0; p < 8; p++) {
        float2 f0 = unpack2(acc[p][0]);
        float2 f1 = unpack2(acc[p][1]);
        *(ull*)&outp[(ag0 + 2*p    )*OD + c0] = pack2(f0.x, f1.x);
        *(ull*)&outp[(ag0 + 2*p + 1)*OD + c0] = pack2(f0.y, f1.y);
    }
}

// ---------------------------------------------------------------------------
// Ally passing path (R4 version, measured 236us)
__global__ void __launch_bounds__(128) ally_pass_kernel(
    const float* __restrict__ feats,
    const float* __restrict__ W1, const float* __restrict__ B1,
    const float* __restrict__ pb1, const float* __restrict__ pw2,
    const float* __restrict__ pb2)
{
    __shared__ __align__(16) float a_sh[KK*16];
    __shared__ __align__(16) float h_sh[HH*16];
    __shared__ __align__(16) float e_sh[16*FD];
    const int tid = threadIdx.x;
    const int r0 = blockIdx.x;
    const int rowbase = r0 * NALLY;

    for (int idx = tid; idx < 16*FD; idx += 128) {
        float v = 0.f;
        if (idx < NALLY*FD) v = feats[rowbase*FD + idx];
        e_sh[idx] = v;
    }
    __syncthreads();

#pragma unroll
    for (int p = 0; p < 8; p++) {
        int idx = tid + p*128;
        int rr = idx & 15, k = idx >> 4;
        float s = 0.f;
        if (rr < NALLY) {
            s = B1[k];
#pragma unroll
            for (int i = 0; i < FD; i++) s = fmaf(e_sh[rr*FD + i], __ldg(W1 + i*HH + k), s);
            s = fmaxf(s, 0.f);
        }
        h_sh[idx] = s;
    }
    __syncthreads();

    for (int idx = tid; idx < KK*16; idx += 128) {
        int kk = idx >> 4, rr = idx & 15;
        float v;
        if (kk < 640) {
            int k = kk / 10, i = kk - k*10;
            v = h_sh[k*16 + rr] * e_sh[rr*FD + i];
        } else {
            v = e_sh[rr*FD + (kk - 640)];
        }
        a_sh[idx] = v;
    }
    __syncthreads();

    const int c0 = tid * 2;
    ull acc[8][2];
#pragma unroll
    for (int p = 0; p < 8; p++) { acc[p][0] = 0ull; acc[p][1] = 0ull; }

#pragma unroll 10
    for (int kk = 0; kk < KK; kk++) {
        float2 wv = __ldg((const float2*)(g_W2p + kk*OD + c0));
        ull w0 = pack2(wv.x, wv.x), w1d = pack2(wv.y, wv.y);
        const ulonglong2* ar = (const ulonglong2*)(a_sh + kk*16);
#pragma unroll
        for (int q = 0; q < 4; q++) {
            ulonglong2 av = ar[q];
            acc[2*q  ][0] = ffma2(av.x, w0,  acc[2*q  ][0]);
            acc[2*q  ][1] = ffma2(av.x, w1d, acc[2*q  ][1]);
            acc[2*q+1][0] = ffma2(av.y, w0,  acc[2*q+1][0]);
            acc[2*q+1][1] = ffma2(av.y, w1d, acc[2*q+1][1]);
        }
    }

    __syncthreads();
    float* t_sh = a_sh;
    const float bb0 = pb1[c0 & 63];
    const float bb1 = pb1[(c0 + 1) & 63];
#pragma unroll
    for (int p = 0; p < 8; p++) {
        float2 f0 = unpack2(acc[p][0]);
        float2 f1 = unpack2(acc[p][1]);
        *(ull*)(t_sh + c0*20 + 2*p)     = pack2(fmaxf(f0.x + bb0, 0.f), fmaxf(f0.y + bb0, 0.f));
        *(ull*)(t_sh + (c0+1)*20 + 2*p) = pack2(fmaxf(f1.x + bb1, 0.f), fmaxf(f1.y + bb1, 0.f));
    }
    __syncthreads();

    float* p_sh = h_sh;
    if (tid < 96) {
        int hd = tid / 24, rem = tid - hd*24, cc = rem >> 3, rp = rem & 7;
        ull ap = 0ull;
#pragma unroll 8
        for (int m = 0; m < 64; m++) {
            float wv = __ldg(pw2 + m*3 + cc);
            ull wd = pack2(wv, wv);
            ull tv = *(const ull*)(t_sh + (hd*64 + m)*20 + 2*rp);
            ap = ffma2(tv, wd, ap);
        }
        float2 f = unpack2(ap);
        p_sh[(hd*3 + cc)*16 + 2*rp]     = f.x;
        p_sh[(hd*3 + cc)*16 + 2*rp + 1] = f.y;
    }
    __syncthreads();

    if (tid < 3) {
        float mx = -INFINITY;
        float bb = pb2[tid];
        for (int row = 0; row < NALLY; row++) {
            float v = 0.25f * (p_sh[(0*3 + tid)*16 + row] + p_sh[(1*3 + tid)*16 + row] +
                               p_sh[(2*3 + tid)*16 + row] + p_sh[(3*3 + tid)*16 + row]) + bb;
            mx = fmaxf(mx, v);
        }
        g_PassEmb[r0*3 + tid] = mx;
    }
}

// ---------------------------------------------------------------------------
// Final: 8 agents per block (512 thr), L1-reused weights, 2-way ILP chains.
__global__ void __launch_bounds__(512) final_kernel(
    const float* __restrict__ own,
    const float* __restrict__ fc1_w, const float* __restrict__ fc1_b,
    const float* __restrict__ merger_w,
    const float* __restrict__ hstate,
    const float* __restrict__ wih, const float* __restrict__ whh,
    const float* __restrict__ bih, const float* __restrict__ bhh,
    const float* __restrict__ fc2_w1, const float* __restrict__ fc2_b1,
    const float* __restrict__ fc2_w2, const float* __restrict__ fc2_b2,
    float* __restrict__ out_q, float* __restrict__ out_h) {
    __shared__ float own_sh[8][32], x_sh[8][64], h_sh[8][64], hh_sh[8][64], t_sh[8][64];
    const int tid = threadIdx.x;
    const int a = tid >> 6, j = tid & 63;
    const int r = blockIdx.x * 8 + a;

    if (j < 30) own_sh[a][j] = own[r*30 + j];
    h_sh[a][j] = hstate[r*64 + j];
    __syncthreads();

    float eo = fc1_b[j];
#pragma unroll
    for (int i = 0; i < 30; i += 2) {
        eo = fmaf(own_sh[a][i], __ldg(fc1_w + i*64 + j), eo);
        eo = fmaf(own_sh[a][i+1], __ldg(fc1_w + (i+1)*64 + j), eo);
    }

    float w0 = merger_w[j], w1v = merger_w[64+j], w2v = merger_w[128+j], w3v = merger_w[192+j];
    float mx = fmaxf(fmaxf(w0, w1v), fmaxf(w2v, w3v));
    float e0 = expf(w0-mx), e1 = expf(w1v-mx), e2 = expf(w2v-mx), e3 = expf(w3v-mx);
    float inv = 1.f / (e0+e1+e2+e3);
    const float* en = g_EmbEn + r*OD;
    const float* al = g_EmbAlSum + r*OD;
    float m = e0*inv*(en[j] + al[j]) + e1*inv*(en[64+j] + al[64+j])
            + e2*inv*(en[128+j] + al[128+j]) + e3*inv*(en[192+j] + al[192+j]);

    x_sh[a][j] = fmaxf(eo + m, 0.f);
    __syncthreads();

    float gi[3], gh[3];
#pragma unroll
    for (int t = 0; t < 3; t++) {
        int g = t*64 + j;
        float si0 = bih[g], si1 = 0.f, sh0 = bhh[g], sh1 = 0.f;
        const float4* wi4 = (const float4*)(wih + g*64);
        const float4* wh4 = (const float4*)(whh + g*64);
#pragma unroll
        for (int k4 = 0; k4 < 16; k4 += 2) {
            float4 a0 = __ldg(wi4 + k4), a1 = __ldg(wi4 + k4 + 1);
            float4 b0 = __ldg(wh4 + k4), b1 = __ldg(wh4 + k4 + 1);
            int kb = 4*k4;
            si0 = fmaf(x_sh[a][kb+0], a0.x, si0); si1 = fmaf(x_sh[a][kb+4], a1.x, si1);
            si0 = fmaf(x_sh[a][kb+1], a0.y, si0); si1 = fmaf(x_sh[a][kb+5], a1.y, si1);
            si0 = fmaf(x_sh[a][kb+2], a0.z, si0); si1 = fmaf(x_sh[a][kb+6], a1.z, si1);
            si0 = fmaf(x_sh[a][kb+3], a0.w, si0); si1 = fmaf(x_sh[a][kb+7], a1.w, si1);
            sh0 = fmaf(h_sh[a][kb+0], b0.x, sh0); sh1 = fmaf(h_sh[a][kb+4], b1.x, sh1);
            sh0 = fmaf(h_sh[a][kb+1], b0.y, sh0); sh1 = fmaf(h_sh[a][kb+5], b1.y, sh1);
            sh0 = fmaf(h_sh[a][kb+2], b0.z, sh0); sh1 = fmaf(h_sh[a][kb+6], b1.z, sh1);
            sh0 = fmaf(h_sh[a][kb+3], b0.w, sh0); sh1 = fmaf(h_sh[a][kb+7], b1.w, sh1);
        }
        gi[t] = si0 + si1; gh[t] = sh0 + sh1;
    }
    float rg = 1.f/(1.f + expf(-(gi[0]+gh[0])));
    float zg = 1.f/(1.f + expf(-(gi[1]+gh[1])));
    float ng = tanhf(gi[2] + rg*gh[2]);
    float hh = (1.f - zg)*ng + zg*h_sh[a][j];
    hh_sh[a][j] = hh;
    out_h[r*64 + j] = hh;
    __syncthreads();

    float tt0 = fc2_b1[j], tt1 = 0.f;
#pragma unroll
    for (int k = 0; k < 64; k += 2) {
        tt0 = fmaf(hh_sh[a][k],   __ldg(fc2_w1 + k*64 + j),     tt0);
        tt1 = fmaf(hh_sh[a][k+1], __ldg(fc2_w1 + (k+1)*64 + j), tt1);
    }
    t_sh[a][j] = fmaxf(tt0 + tt1, 0.f);
    __syncthreads();

    if (j < 19) {
        float q0 = fc2_b2[j], q1 = 0.f;
#pragma unroll
        for (int mm = 0; mm < 64; mm += 2) {
            q0 = fmaf(t_sh[a][mm],   __ldg(fc2_w2 + mm*19 + j),     q0);
            q1 = fmaf(t_sh[a][mm+1], __ldg(fc2_w2 + (mm+1)*19 + j), q1);
        }
        int col = (j < 9) ? j : j + 3;
        out_q[r*22 + col] = q0 + q1;
    }
    if (j < 3) out_q[r*22 + 9 + j] = g_PassEmb[r*3 + j];
}

extern "C" void kernel_launch(void* const* d_in, const int* in_sizes, int n_in,
                              void* d_out, int out_size) {
    const float* own    = (const float*)d_in[1];
    const float* ally   = (const float*)d_in[2];
    const float* enemy  = (const float*)d_in[3];
    const float* hstate = (const float*)d_in[4];
    const float* fc1_w  = (const float*)d_in[5];
    const float* fc1_b  = (const float*)d_in[6];
    const float* he_w1  = (const float*)d_in[7];
    const float* he_b1  = (const float*)d_in[8];
    const float* he_w2  = (const float*)d_in[9];
    const float* he_b2  = (const float*)d_in[10];
    const float* ha_w1  = (const float*)d_in[11];
    const float* ha_b1  = (const float*)d_in[12];
    const float* ha_w2  = (const float*)d_in[13];
    const float* ha_b2  = (const float*)d_in[14];
    const float* merger = (const float*)d_in[15];
    const float* wih    = (const float*)d_in[16];
    const float* whh    = (const float*)d_in[17];
    const float* bih    = (const float*)d_in[18];
    const float* bhh    = (const float*)d_in[19];
    const float* fc2_w1 = (const float*)d_in[20];
    const float* fc2_b1 = (const float*)d_in[21];
    const float* fc2_w2 = (const float*)d_in[22];
    const float* fc2_b2 = (const float*)d_in[23];
    const float* pw1    = (const float*)d_in[24];
    const float* pb1    = (const float*)d_in[25];
    const float* pw2    = (const float*)d_in[26];
    const float* pb2    = (const float*)d_in[27];

    float* out   = (float*)d_out;
    float* out_q = out;              // [2048, 22]
    float* out_h = out + RR*22;      // [2048, 64]

    w2p_kernel<<<KK, 256>>>(ha_w2, ha_b2, pw1);
    summed_kernel<NEN,   true ><<<RR/16, 128>>>(enemy, he_w1, he_b1, he_w2, he_b2, 2820);
    summed_kernel<NALLY, false><<<RR/16, 128>>>(ally,  ha_w1, ha_b1, ha_w2, ha_b2, 2560);
    ally_pass_kernel<<<RR, 128>>>(ally, ha_w1, ha_b1, pb1, pw2, pb2);
    final_kernel<<<RR/8, 512>>>(own, fc1_w, fc1_b, merger, hstate,
                                wih, whh, bih, bhh,
                                fc2_w1, fc2_b1, fc2_w2, fc2_b2,
                                out_q, out_h);
}

// round 10
// speedup vs baseline: 1.9159x; 1.3276x over previous
#include <cuda_runtime.h>
#include <cuda_bf16.h>
#include <math.h>

#define RR 2048
#define NEN 16
#define NALLY 15
#define HH 64
#define OD 256
#define FD 10
#define KK 650
#define KPAD 704
#define NCHUNK 11

__device__ float g_EmbEn[RR*OD];
__device__ float g_EmbAlSum[RR*OD];
__device__ float g_Pd[RR*NALLY*3];
__device__ __nv_bfloat16 g_Bhi[KPAD*OD];
__device__ __nv_bfloat16 g_Blo[KPAD*OD];

typedef unsigned long long ull;
typedef unsigned int u32;

__device__ __forceinline__ ull ffma2(ull a, ull b, ull c) {
    ull d; asm("fma.rn.f32x2 %0, %1, %2, %3;" : "=l"(d) : "l"(a), "l"(b), "l"(c)); return d;
}
__device__ __forceinline__ ull pack2(float x, float y) {
    ull d; asm("mov.b64 %0, {%1, %2};" : "=l"(d) : "f"(x), "f"(y)); return d;
}
__device__ __forceinline__ float2 unpack2(ull v) {
    float2 r; asm("mov.b64 {%0, %1}, %2;" : "=f"(r.x), "=f"(r.y) : "l"(v)); return r;
}
__device__ __forceinline__ u32 smem_u32(const void* p) {
    u32 a; asm("{ .reg .u64 t; cvta.to.shared.u64 t, %1; cvt.u32.u64 %0, t; }" : "=r"(a) : "l"(p)); return a;
}
__device__ __forceinline__ void ldmA(u32* r, u32 addr) {
    asm volatile("ldmatrix.sync.aligned.m8n8.x4.shared.b16 {%0,%1,%2,%3}, [%4];"
        : "=r"(r[0]), "=r"(r[1]), "=r"(r[2]), "=r"(r[3]) : "r"(addr));
}
__device__ __forceinline__ void ldmB(u32* r, u32 addr) {
    asm volatile("ldmatrix.sync.aligned.m8n8.x2.trans.shared.b16 {%0,%1}, [%2];"
        : "=r"(r[0]), "=r"(r[1]) : "r"(addr));
}
__device__ __forceinline__ void mma16816(float* d, const u32* a, const u32* b) {
    asm volatile("mma.sync.aligned.m16n8k16.row.col.f32.bf16.bf16.f32 "
        "{%0,%1,%2,%3},{%4,%5,%6,%7},{%8,%9},{%0,%1,%2,%3};"
        : "+f"(d[0]), "+f"(d[1]), "+f"(d[2]), "+f"(d[3])
        : "r"(a[0]), "r"(a[1]), "r"(a[2]), "r"(a[3]), "r"(b[0]), "r"(b[1]));
}

// ---------------------------------------------------------------------------
// W2p rows -> split bf16 hi/lo images [KPAD][256] (zero pad kk>=650)
__global__ void __launch_bounds__(256) w2p_kernel(const float* __restrict__ ha_w2,
        const float* __restrict__ ha_b2, const float* __restrict__ pw1) {
    __shared__ float wrow[256];
    const int kk = blockIdx.x, o = threadIdx.x;
    float v = 0.f;
    if (kk < KK) {
        float w;
        if (kk < 640) { int k = kk/10, i = kk - k*10; w = ha_w2[k*2560 + i*256 + o]; }
        else          w = ha_b2[(kk-640)*256 + o];
        wrow[o] = w;
    }
    __syncthreads();
    if (kk < KK) {
        const int hd = o >> 6, j = o & 63;
        float s = 0.f;
#pragma unroll
        for (int h = 0; h < 64; h++) s = fmaf(wrow[hd*64 + h], __ldg(pw1 + h*64 + j), s);
        v = s;
    }
    __nv_bfloat16 hi = __float2bfloat16(v);
    __nv_bfloat16 lo = __float2bfloat16(v - __bfloat162float(hi));
    g_Bhi[kk*256 + o] = hi;
    g_Blo[kk*256 + o] = lo;
}

// ---------------------------------------------------------------------------
// Summed bilinear (R4 version, measured-good)
template<int NR, bool ENEMY>
__global__ void __launch_bounds__(128) summed_kernel(
    const float* __restrict__ feats,
    const float* __restrict__ W1, const float* __restrict__ B1,
    const float* __restrict__ W2, const float* __restrict__ B2, int strideK)
{
    __shared__ __align__(16) float a_sh[KK*16];
    __shared__ float e_sh[16*161];
    const int tid = threadIdx.x;
    const int ag0 = blockIdx.x * 16;
    for (int idx = tid; idx < 16*NR*FD; idx += 128) {
        int a = idx / (NR*FD), rem = idx - a*(NR*FD);
        e_sh[a*161 + rem] = feats[(ag0*NR)*FD + idx];
    }
    __syncthreads();
#pragma unroll
    for (int p = 0; p < 8; p++) {
        int idx = tid + p*128;
        int a = idx & 15, k = idx >> 4;
        const float* ea = e_sh + a*161;
        float h[NR];
#pragma unroll
        for (int rr = 0; rr < NR; rr++) {
            float s = B1[k];
#pragma unroll
            for (int i = 0; i < FD; i++) s = fmaf(ea[rr*FD + i], __ldg(W1 + i*HH + k), s);
            h[rr] = fmaxf(s, 0.f);
        }
#pragma unroll
        for (int i = 0; i < FD; i++) {
            float s = 0.f;
#pragma unroll
            for (int rr = 0; rr < NR; rr++) s = fmaf(h[rr], ea[rr*FD + i], s);
            a_sh[(k*10 + i)*16 + a] = s;
        }
    }
    for (int idx = tid; idx < 160; idx += 128) {
        int a = idx & 15, i = idx >> 4;
        const float* ea = e_sh + a*161;
        float s = 0.f;
#pragma unroll
        for (int rr = 0; rr < NR; rr++) s += ea[rr*FD + i];
        a_sh[(640 + i)*16 + a] = s;
    }
    __syncthreads();
    const int c0 = tid * 2;
    ull acc[8][2];
#pragma unroll
    for (int p = 0; p < 8; p++) { acc[p][0] = 0ull; acc[p][1] = 0ull; }
    for (int k = 0; k < 64; k++) {
        const float* wk = W2 + k*strideK + c0;
#pragma unroll
        for (int i = 0; i < 10; i++) {
            float2 wv = __ldg((const float2*)(wk + i*OD));
            ull w0 = pack2(wv.x, wv.x), w1d = pack2(wv.y, wv.y);
            const ulonglong2* ar = (const ulonglong2*)(a_sh + (k*10 + i)*16);
#pragma unroll
            for (int q = 0; q < 4; q++) {
                ulonglong2 av = ar[q];
                acc[2*q  ][0] = ffma2(av.x, w0,  acc[2*q  ][0]);
                acc[2*q  ][1] = ffma2(av.x, w1d, acc[2*q  ][1]);
                acc[2*q+1][0] = ffma2(av.y, w0,  acc[2*q+1][0]);
                acc[2*q+1][1] = ffma2(av.y, w1d, acc[2*q+1][1]);
            }
        }
    }
#pragma unroll
    for (int i = 0; i < 10; i++) {
        float2 wv = __ldg((const float2*)(B2 + i*OD + c0));
        ull w0 = pack2(wv.x, wv.x), w1d = pack2(wv.y, wv.y);
        const ulonglong2* ar = (const ulonglong2*)(a_sh + (640 + i)*16);
#pragma unroll
        for (int q = 0; q < 4; q++) {
            ulonglong2 av = ar[q];
            acc[2*q  ][0] = ffma2(av.x, w0,  acc[2*q  ][0]);
            acc[2*q  ][1] = ffma2(av.x, w1d, acc[2*q  ][1]);
            acc[2*q+1][0] = ffma2(av.y, w0,  acc[2*q+1][0]);
            acc[2*q+1][1] = ffma2(av.y, w1d, acc[2*q+1][1]);
        }
    }
    float* outp = ENEMY ? g_EmbEn : g_EmbAlSum;
#pragma unroll
    for (int p = 0; p < 8; p++) {
        float2 f0 = unpack2(acc[p][0]);
        float2 f1 = unpack2(acc[p][1]);
        *(ull*)&outp[(ag0 + 2*p    )*OD + c0] = pack2(f0.x, f1.x);
        *(ull*)&outp[(ag0 + 2*p + 1)*OD + c0] = pack2(f0.y, f1.y);
    }
}

// ---------------------------------------------------------------------------
// Ally layer-1 via mma.sync bf16 3-pass split + fused relu/pw2/head-mean.
// 480 blocks x 256 thr; 64 flat ally rows per block; N=256; K chunks of 64.
#define ASTR 144            // A smem row stride bytes (72 bf16)
#define BSTR 528            // B smem row stride bytes (264 bf16)
#define SA_HI 0
#define SA_LO 9216
#define SB_HI 18432
#define SB_LO 52224
#define SE    86016
#define SH    88576
#define SW1   90624
#define SB1   93184
#define SPWE  93440
#define SPD   94464
#define SM_TOT 100608

__global__ void __launch_bounds__(256) ally_mma_kernel(
    const float* __restrict__ feats, const float* __restrict__ W1, const float* __restrict__ B1,
    const float* __restrict__ pb1, const float* __restrict__ pw2, const float* __restrict__ pb2)
{
    extern __shared__ __align__(1024) char smem[];
    const int tid = threadIdx.x;
    const int w = tid >> 5, l = tid & 31;
    const u32 sb = smem_u32(smem);
    const int base = blockIdx.x * 64;

    float* e_sh  = (float*)(smem + SE);     // [i][m]
    float* h_sh  = (float*)(smem + SH);     // [k-k0][m]
    float* w1_sh = (float*)(smem + SW1);
    float* b1_sh = (float*)(smem + SB1);
    float* pwe   = (float*)(smem + SPWE);
    float* pd_sh = (float*)(smem + SPD);    // [8][64][3]

    for (int idx = tid; idx < 640; idx += 256) {
        int m = idx / 10, i = idx - m*10;
        e_sh[i*64 + m] = __ldg(feats + (size_t)base*FD + idx);
        w1_sh[idx] = __ldg(W1 + idx);
    }
    if (tid < 64) b1_sh[tid] = B1[tid];
    if (tid < 256) pwe[tid] = (tid < 64) ? __ldg(pb1 + tid) : __ldg(pw2 + tid - 64);
    __syncthreads();

    float d[4][4][4];
#pragma unroll
    for (int a = 0; a < 4; a++)
#pragma unroll
        for (int b = 0; b < 4; b++)
#pragma unroll
            for (int q = 0; q < 4; q++) d[a][b][q] = 0.f;

    const int m64 = tid & 63, part = tid >> 6;

    for (int c = 0; c < NCHUNK; c++) {
        __syncthreads();   // previous mma done reading smem

        // h for this chunk's k-range
        const int k0 = (c*64) / 10;
        const int kcnt = (c < 10) ? ((c*64 + 63)/10 - k0 + 1) : 0;
        for (int idx = tid; idx < kcnt*64; idx += 256) {
            int kr = idx >> 6, mm = idx & 63;
            float s = b1_sh[k0 + kr];
#pragma unroll
            for (int i = 0; i < FD; i++) s = fmaf(e_sh[i*64 + mm], w1_sh[i*64 + k0 + kr], s);
            h_sh[kr*64 + mm] = fmaxf(s, 0.f);
        }
        if (kcnt) __syncthreads();

        // A build: thread (part, m64): kk in [c*64+part*16, +16)
        {
            u32 hi[8], lo[8];
#pragma unroll
            for (int u = 0; u < 8; u++) {
                float x[2];
#pragma unroll
                for (int v2 = 0; v2 < 2; v2++) {
                    int kk = c*64 + part*16 + 2*u + v2;
                    float xv;
                    if (kk < 640) {
                        int k = (kk*6554) >> 16, i = kk - k*10;
                        xv = h_sh[(k - k0)*64 + m64] * e_sh[i*64 + m64];
                    } else if (kk < KK) xv = e_sh[(kk - 640)*64 + m64];
                    else xv = 0.f;
                    x[v2] = xv;
                }
                __nv_bfloat16 h0 = __float2bfloat16(x[0]), h1 = __float2bfloat16(x[1]);
                __nv_bfloat16 g0 = __float2bfloat16(x[0] - __bfloat162float(h0));
                __nv_bfloat16 g1 = __float2bfloat16(x[1] - __bfloat162float(h1));
                hi[u] = ((u32)__bfloat16_as_ushort(h1) << 16) | __bfloat16_as_ushort(h0);
                lo[u] = ((u32)__bfloat16_as_ushort(g1) << 16) | __bfloat16_as_ushort(g0);
            }
            int off = m64*ASTR + part*32;
            *(uint4*)(smem + SA_HI + off)      = make_uint4(hi[0], hi[1], hi[2], hi[3]);
            *(uint4*)(smem + SA_HI + off + 16) = make_uint4(hi[4], hi[5], hi[6], hi[7]);
            *(uint4*)(smem + SA_LO + off)      = make_uint4(lo[0], lo[1], lo[2], lo[3]);
            *(uint4*)(smem + SA_LO + off + 16) = make_uint4(lo[4], lo[5], lo[6], lo[7]);
        }
        // B stage (32KB hi + 32KB lo)
        for (int s = tid; s < 2048; s += 256) {
            int row = s >> 5, col = s & 31;
            *(uint4*)(smem + SB_HI + row*BSTR + col*16) =
                *(const uint4*)(g_Bhi + (size_t)(c*64 + row)*256 + col*8);
            *(uint4*)(smem + SB_LO + row*BSTR + col*16) =
                *(const uint4*)(g_Blo + (size_t)(c*64 + row)*256 + col*8);
        }
        __syncthreads();

        // MMA phase: warp w covers n-tiles 4w..4w+3
        const u32 aRow = (u32)((l & 15)*ASTR + (l >> 4)*16);
#pragma unroll
        for (int kt = 0; kt < 4; kt++) {
            u32 ah[4][4], al_[4][4];
#pragma unroll
            for (int mt = 0; mt < 4; mt++) {
                u32 ab = sb + (u32)(mt*16*ASTR) + aRow + (u32)(kt*32);
                ldmA(ah[mt],  ab + SA_HI);
                ldmA(al_[mt], ab + SA_LO);
            }
#pragma unroll
            for (int nt = 0; nt < 4; nt++) {
                u32 bh[2], bl[2];
                u32 baddr = sb + SB_HI + (u32)((kt*16 + (l & 15))*BSTR + (w*4 + nt)*16);
                ldmB(bh, baddr);
                ldmB(bl, baddr + (SB_LO - SB_HI));
#pragma unroll
                for (int mt = 0; mt < 4; mt++) {
                    mma16816(d[mt][nt], ah[mt],  bh);
                    mma16816(d[mt][nt], ah[mt],  bl);
                    mma16816(d[mt][nt], al_[mt], bh);
                }
            }
        }
    }

    // Epilogue: t=relu(z+pb1[col&63]); pd_c += t*pw2[(col&63)*3+c]; quad-reduce
    float pdl[4][2][3];
#pragma unroll
    for (int mt = 0; mt < 4; mt++)
#pragma unroll
        for (int h = 0; h < 2; h++)
#pragma unroll
            for (int cc = 0; cc < 3; cc++) pdl[mt][h][cc] = 0.f;

#pragma unroll
    for (int mt = 0; mt < 4; mt++) {
#pragma unroll
        for (int nt = 0; nt < 4; nt++) {
            int colA = (w*4 + nt)*8 + (l & 3)*2;
            int jA = colA & 63, jB = (colA + 1) & 63;
#pragma unroll
            for (int h = 0; h < 2; h++) {
                float t0 = fmaxf(d[mt][nt][2*h    ] + pwe[jA], 0.f);
                float t1 = fmaxf(d[mt][nt][2*h + 1] + pwe[jB], 0.f);
#pragma unroll
                for (int cc = 0; cc < 3; cc++) {
                    pdl[mt][h][cc] = fmaf(t0, pwe[64 + jA*3 + cc], pdl[mt][h][cc]);
                    pdl[mt][h][cc] = fmaf(t1, pwe[64 + jB*3 + cc], pdl[mt][h][cc]);
                }
            }
        }
    }
#pragma unroll
    for (int mt = 0; mt < 4; mt++)
#pragma unroll
        for (int h = 0; h < 2; h++)
#pragma unroll
            for (int cc = 0; cc < 3; cc++) {
                float v = pdl[mt][h][cc];
                v += __shfl_xor_sync(0xffffffffu, v, 1);
                v += __shfl_xor_sync(0xffffffffu, v, 2);
                pdl[mt][h][cc] = v;
            }
    if ((l & 3) == 0) {
        int q = l >> 2;
#pragma unroll
        for (int mt = 0; mt < 4; mt++)
#pragma unroll
            for (int h = 0; h < 2; h++) {
                int row = mt*16 + q + 8*h;
#pragma unroll
                for (int cc = 0; cc < 3; cc++)
                    pd_sh[(w*64 + row)*3 + cc] = pdl[mt][h][cc];
            }
    }
    __syncthreads();
    if (tid < 192) {
        int row = tid / 3, cc = tid - row*3;
        float s = 0.f;
#pragma unroll
        for (int ww = 0; ww < 8; ww++) s += pd_sh[(ww*64 + row)*3 + cc];
        g_Pd[(size_t)(base + row)*3 + cc] = 0.25f*s + __ldg(pb2 + cc);
    }
}

// ---------------------------------------------------------------------------
// Final: 8 agents per block (512 thr); passing max over g_Pd.
__global__ void __launch_bounds__(512) final_kernel(
    const float* __restrict__ own,
    const float* __restrict__ fc1_w, const float* __restrict__ fc1_b,
    const float* __restrict__ merger_w,
    const float* __restrict__ hstate,
    const float* __restrict__ wih, const float* __restrict__ whh,
    const float* __restrict__ bih, const float* __restrict__ bhh,
    const float* __restrict__ fc2_w1, const float* __restrict__ fc2_b1,
    const float* __restrict__ fc2_w2, const float* __restrict__ fc2_b2,
    float* __restrict__ out_q, float* __restrict__ out_h) {
    __shared__ float own_sh[8][32], x_sh[8][64], h_sh[8][64], hh_sh[8][64], t_sh[8][64];
    const int tid = threadIdx.x;
    const int a = tid >> 6, j = tid & 63;
    const int r = blockIdx.x * 8 + a;

    if (j < 30) own_sh[a][j] = own[r*30 + j];
    h_sh[a][j] = hstate[r*64 + j];
    __syncthreads();

    float eo = fc1_b[j];
#pragma unroll
    for (int i = 0; i < 30; i += 2) {
        eo = fmaf(own_sh[a][i], __ldg(fc1_w + i*64 + j), eo);
        eo = fmaf(own_sh[a][i+1], __ldg(fc1_w + (i+1)*64 + j), eo);
    }

    float w0 = merger_w[j], w1v = merger_w[64+j], w2v = merger_w[128+j], w3v = merger_w[192+j];
    float mx = fmaxf(fmaxf(w0, w1v), fmaxf(w2v, w3v));
    float e0 = expf(w0-mx), e1 = expf(w1v-mx), e2 = expf(w2v-mx), e3 = expf(w3v-mx);
    float inv = 1.f / (e0+e1+e2+e3);
    const float* en = g_EmbEn + r*OD;
    const float* al = g_EmbAlSum + r*OD;
    float m = e0*inv*(en[j] + al[j]) + e1*inv*(en[64+j] + al[64+j])
            + e2*inv*(en[128+j] + al[128+j]) + e3*inv*(en[192+j] + al[192+j]);

    x_sh[a][j] = fmaxf(eo + m, 0.f);
    __syncthreads();

    float gi[3], gh[3];
#pragma unroll
    for (int t = 0; t < 3; t++) {
        int g = t*64 + j;
        float si0 = bih[g], si1 = 0.f, sh0 = bhh[g], sh1 = 0.f;
        const float4* wi4 = (const float4*)(wih + g*64);
        const float4* wh4 = (const float4*)(whh + g*64);
#pragma unroll
        for (int k4 = 0; k4 < 16; k4 += 2) {
            float4 a0 = __ldg(wi4 + k4), a1 = __ldg(wi4 + k4 + 1);
            float4 b0 = __ldg(wh4 + k4), b1 = __ldg(wh4 + k4 + 1);
            int kb = 4*k4;
            si0 = fmaf(x_sh[a][kb+0], a0.x, si0); si1 = fmaf(x_sh[a][kb+4], a1.x, si1);
            si0 = fmaf(x_sh[a][kb+1], a0.y, si0); si1 = fmaf(x_sh[a][kb+5], a1.y, si1);
            si0 = fmaf(x_sh[a][kb+2], a0.z, si0); si1 = fmaf(x_sh[a][kb+6], a1.z, si1);
            si0 = fmaf(x_sh[a][kb+3], a0.w, si0); si1 = fmaf(x_sh[a][kb+7], a1.w, si1);
            sh0 = fmaf(h_sh[a][kb+0], b0.x, sh0); sh1 = fmaf(h_sh[a][kb+4], b1.x, sh1);
            sh0 = fmaf(h_sh[a][kb+1], b0.y, sh0); sh1 = fmaf(h_sh[a][kb+5], b1.y, sh1);
            sh0 = fmaf(h_sh[a][kb+2], b0.z, sh0); sh1 = fmaf(h_sh[a][kb+6], b1.z, sh1);
            sh0 = fmaf(h_sh[a][kb+3], b0.w, sh0); sh1 = fmaf(h_sh[a][kb+7], b1.w, sh1);
        }
        gi[t] = si0 + si1; gh[t] = sh0 + sh1;
    }
    float rg = 1.f/(1.f + expf(-(gi[0]+gh[0])));
    float zg = 1.f/(1.f + expf(-(gi[1]+gh[1])));
    float ng = tanhf(gi[2] + rg*gh[2]);
    float hh = (1.f - zg)*ng + zg*h_sh[a][j];
    hh_sh[a][j] = hh;
    out_h[r*64 + j] = hh;
    __syncthreads();

    float tt0 = fc2_b1[j], tt1 = 0.f;
#pragma unroll
    for (int k = 0; k < 64; k += 2) {
        tt0 = fmaf(hh_sh[a][k],   __ldg(fc2_w1 + k*64 + j),     tt0);
        tt1 = fmaf(hh_sh[a][k+1], __ldg(fc2_w1 + (k+1)*64 + j), tt1);
    }
    t_sh[a][j] = fmaxf(tt0 + tt1, 0.f);
    __syncthreads();

    if (j < 19) {
        float q0 = fc2_b2[j], q1 = 0.f;
#pragma unroll
        for (int mm = 0; mm < 64; mm += 2) {
            q0 = fmaf(t_sh[a][mm],   __ldg(fc2_w2 + mm*19 + j),     q0);
            q1 = fmaf(t_sh[a][mm+1], __ldg(fc2_w2 + (mm+1)*19 + j), q1);
        }
        int col = (j < 9) ? j : j + 3;
        out_q[r*22 + col] = q0 + q1;
    }
    if (j < 3) {
        float mxp = -INFINITY;
        for (int q = 0; q < NALLY; q++)
            mxp = fmaxf(mxp, g_Pd[(size_t)(r*NALLY + q)*3 + j]);
        out_q[r*22 + 9 + j] = mxp;
    }
}

extern "C" void kernel_launch(void* const* d_in, const int* in_sizes, int n_in,
                              void* d_out, int out_size) {
    const float* own    = (const float*)d_in[1];
    const float* ally   = (const float*)d_in[2];
    const float* enemy  = (const float*)d_in[3];
    const float* hstate = (const float*)d_in[4];
    const float* fc1_w  = (const float*)d_in[5];
    const float* fc1_b  = (const float*)d_in[6];
    const float* he_w1  = (const float*)d_in[7];
    const float* he_b1  = (const float*)d_in[8];
    const float* he_w2  = (const float*)d_in[9];
    const float* he_b2  = (const float*)d_in[10];
    const float* ha_w1  = (const float*)d_in[11];
    const float* ha_b1  = (const float*)d_in[12];
    const float* ha_w2  = (const float*)d_in[13];
    const float* ha_b2  = (const float*)d_in[14];
    const float* merger = (const float*)d_in[15];
    const float* wih    = (const float*)d_in[16];
    const float* whh    = (const float*)d_in[17];
    const float* bih    = (const float*)d_in[18];
    const float* bhh    = (const float*)d_in[19];
    const float* fc2_w1 = (const float*)d_in[20];
    const float* fc2_b1 = (const float*)d_in[21];
    const float* fc2_w2 = (const float*)d_in[22];
    const float* fc2_b2 = (const float*)d_in[23];
    const float* pw1    = (const float*)d_in[24];
    const float* pb1    = (const float*)d_in[25];
    const float* pw2    = (const float*)d_in[26];
    const float* pb2    = (const float*)d_in[27];

    float* out   = (float*)d_out;
    float* out_q = out;              // [2048, 22]
    float* out_h = out + RR*22;      // [2048, 64]

    static int once = 0;
    if (!once) {
        cudaFuncSetAttribute(ally_mma_kernel, cudaFuncAttributeMaxDynamicSharedMemorySize, SM_TOT);
        once = 1;
    }

    w2p_kernel<<<KPAD, 256>>>(ha_w2, ha_b2, pw1);
    summed_kernel<NEN,   true ><<<RR/16, 128>>>(enemy, he_w1, he_b1, he_w2, he_b2, 2820);
    summed_kernel<NALLY, false><<<RR/16, 128>>>(ally,  ha_w1, ha_b1, ha_w2, ha_b2, 2560);
    ally_mma_kernel<<<480, 256, SM_TOT>>>(ally, ha_w1, ha_b1, pb1, pw2, pb2);
    final_kernel<<<RR/8, 512>>>(own, fc1_w, fc1_b, merger, hstate,
                                wih, whh, bih, bhh,
                                fc2_w1, fc2_b1, fc2_w2, fc2_b2,
                                out_q, out_h);
}